// round 1
// baseline (speedup 1.0000x reference)
#include <cuda_runtime.h>
#include <math.h>

// Problem constants (fixed by setup_inputs): E=800000, M=9, H=4, D=16, CV=8, N=50000
#define HH   4
#define MM   9
#define DD   16
#define EPSF 1e-16f

static const int NODES_CAP = 262144;          // >= num_nodes (50000), headroom
static const int EH_CAP    = 3200000 + 256;   // >= E*H

// Scratch (allocation-free: __device__ globals)
__device__ float g_segmax[NODES_CAP * HH];
__device__ float g_segsum[NODES_CAP * HH];
__device__ float g_buf[EH_CAP];               // pre -> ex -> att, reused in place

// float atomic max via int/uint ordering trick (valid for all finite + -inf init)
__device__ __forceinline__ void atomicMaxF(float* addr, float v) {
    if (v >= 0.0f)
        atomicMax(reinterpret_cast<int*>(addr), __float_as_int(v));
    else
        atomicMin(reinterpret_cast<unsigned int*>(addr), __float_as_uint(v));
}

// ---------------- Kernel 1: init segment tables ----------------
__global__ void k_init() {
    int i = blockIdx.x * blockDim.x + threadIdx.x;
    if (i < NODES_CAP * HH) {
        g_segmax[i] = -INFINITY;
        g_segsum[i] = 0.0f;
    }
}

// ---------------- Kernel 2: pre[e,h] = 0.25 * sum_{m,d} q*k ; seg max ----------------
__global__ void k_pre(const float* __restrict__ q, const float* __restrict__ kk,
                      const int* __restrict__ index, int EH) {
    int t = blockIdx.x * blockDim.x + threadIdx.x;
    if (t >= EH) return;
    int e = t >> 2;
    int h = t & 3;

    const float4* qp = reinterpret_cast<const float4*>(q  + (size_t)e * (MM*HH*DD) + h * DD);
    const float4* kp = reinterpret_cast<const float4*>(kk + (size_t)e * (MM*HH*DD) + h * DD);

    float s = 0.0f;
#pragma unroll
    for (int m = 0; m < MM; m++) {
#pragma unroll
        for (int j = 0; j < 4; j++) {
            // row stride between m's: H*D = 64 floats = 16 float4
            float4 a = qp[m * 16 + j];
            float4 b = kp[m * 16 + j];
            s = fmaf(a.x, b.x, s);
            s = fmaf(a.y, b.y, s);
            s = fmaf(a.z, b.z, s);
            s = fmaf(a.w, b.w, s);
        }
    }
    s *= 0.25f;   // D^-0.5, D=16
    g_buf[t] = s;
    atomicMaxF(&g_segmax[index[e] * HH + h], s);
}

// ---------------- Kernel 3: ex = exp(pre - segmax) ; seg sum ----------------
__global__ void k_ex(const int* __restrict__ index, int EH) {
    int t = blockIdx.x * blockDim.x + threadIdx.x;
    if (t >= EH) return;
    int e = t >> 2;
    int h = t & 3;
    int n = index[e] * HH + h;
    float ex = expf(g_buf[t] - g_segmax[n]);
    g_buf[t] = ex;
    atomicAdd(&g_segsum[n], ex);
}

// ---------------- Kernel 4: att = ex / (sum + eps) ; write att_b output ----------------
__global__ void k_att(const int* __restrict__ index, float* __restrict__ attb, int EH) {
    int t = blockIdx.x * blockDim.x + threadIdx.x;
    if (t >= EH) return;
    int e = t >> 2;
    int h = t & 3;
    int n = index[e] * HH + h;
    float att = g_buf[t] / (g_segsum[n] + EPSF);
    g_buf[t] = att;
    attb[t]  = att;
}

// ---------------- Kernel 5: out[e,m,h*8+c] = att[e,h] * v[e,m,h*8+c] ----------------
// One thread per float4; layout (E, M, 32) -> 8 float4 per (e,m), 2 per head.
__global__ void k_scale(const float4* __restrict__ v4, float4* __restrict__ o4, int total4) {
    int i = blockIdx.x * blockDim.x + threadIdx.x;
    if (i >= total4) return;
    int e   = i / (MM * 8);
    int rem = i - e * (MM * 8);
    int h   = (rem & 7) >> 1;
    float a = g_buf[e * HH + h];
    float4 vv = v4[i];
    float4 oo;
    oo.x = vv.x * a;
    oo.y = vv.y * a;
    oo.z = vv.z * a;
    oo.w = vv.w * a;
    o4[i] = oo;
}

extern "C" void kernel_launch(void* const* d_in, const int* in_sizes, int n_in,
                              void* d_out, int out_size) {
    const float* q     = (const float*)d_in[0];
    const float* k     = (const float*)d_in[1];
    const float* v     = (const float*)d_in[2];
    const int*   index = (const int*)  d_in[3];

    int E     = in_sizes[3];        // number of edges
    int EH    = E * HH;
    int vsize = in_sizes[2];        // E * M * H*CV  (== size of 'out' part)
    int total4 = vsize / 4;

    float* out  = (float*)d_out;
    float* attb = out + vsize;      // att_b region follows out

    const int B = 256;
    k_init <<<(NODES_CAP * HH + B - 1) / B, B>>>();
    k_pre  <<<(EH + B - 1) / B, B>>>(q, k, index, EH);
    k_ex   <<<(EH + B - 1) / B, B>>>(index, EH);
    k_att  <<<(EH + B - 1) / B, B>>>(index, attb, EH);
    k_scale<<<(total4 + B - 1) / B, B>>>((const float4*)v, (float4*)out, total4);
}